// round 15
// baseline (speedup 1.0000x reference)
#include <cuda_runtime.h>
#include <cuda_fp16.h>
#include <math.h>
#include <stdint.h>

#define SEQ 8192
#define DIM 1024

// ---- scratch (__device__ globals; no allocs allowed) ----
__device__ __half g_hX [SEQ * DIM];
__device__ __half g_hWq[DIM * DIM];
__device__ __half g_hWk[DIM * DIM];
__device__ __half g_hWv[DIM * DIM];
__device__ __half g_hQ [SEQ * DIM];
__device__ __half g_hK [SEQ * DIM];
__device__ __half g_hVt[DIM * SEQ];            // V^T (K-major B for PV)
__device__ __half g_hP [(size_t)SEQ * SEQ];    // unscaled exp(s - m_b), half
__device__ float  g_Mb [(size_t)SEQ * 64];     // per (row, block) max
__device__ float  g_Lb [(size_t)SEQ * 64];     // per (row, block) sum
__device__ __half g_sc [(size_t)SEQ * 64];     // per (row, block) scale e^{mb-m}/L
__device__ float  g_part[2048 * DIM];          // PV split-K partials (rows 6144..8191)

// ---------------------------------------------------------------------------
__device__ __forceinline__ uint32_t smem_u32(const void* p) {
    uint32_t a;
    asm("{ .reg .u64 t; cvta.to.shared.u64 t, %1; cvt.u32.u64 %0, t; }" : "=r"(a) : "l"(p));
    return a;
}
__device__ __forceinline__ void mma_f16(float* c, const uint32_t* a, const uint32_t* b) {
    asm volatile(
        "mma.sync.aligned.m16n8k16.row.col.f32.f16.f16.f32 "
        "{%0,%1,%2,%3}, {%4,%5,%6,%7}, {%8,%9}, {%0,%1,%2,%3};\n"
        : "+f"(c[0]), "+f"(c[1]), "+f"(c[2]), "+f"(c[3])
        : "r"(a[0]), "r"(a[1]), "r"(a[2]), "r"(a[3]), "r"(b[0]), "r"(b[1]));
}
__device__ __forceinline__ void ldsm4(uint32_t* r, uint32_t addr) {
    asm volatile("ldmatrix.sync.aligned.m8n8.x4.shared.b16 {%0,%1,%2,%3}, [%4];"
                 : "=r"(r[0]), "=r"(r[1]), "=r"(r[2]), "=r"(r[3]) : "r"(addr));
}
__device__ __forceinline__ uint32_t hmul2_u(uint32_t a, __half2 s) {
    __half2 v = *(__half2*)&a;
    v = __hmul2(v, s);
    return *(uint32_t*)&v;
}
#define CP16(dst, src) \
    asm volatile("cp.async.cg.shared.global [%0], [%1], 16;" :: "r"(dst), "l"(src) : "memory")

#define STAGE_B (2 * 128 * 40 * 2)   // 20480 bytes per stage
#define BOFF    (128 * 40 * 2)

#define PRODUCE(t) do {                                                       \
        const __half* _Ab = Ag + (t) * 32;                                    \
        const __half* _Bb = Bg + (t) * 32;                                    \
        const uint32_t _sA = sbase + ((t) & 3) * STAGE_B;                     \
        const uint32_t _sB = _sA + BOFF;                                      \
        _Pragma("unroll")                                                     \
        for (int _j = 0; _j < 4; _j++) {                                      \
            int _q = _j * 128 + tid;                                          \
            int _r = _q >> 2, _c = _q & 3;                                    \
            uint32_t _so = _r * 80 + _c * 16;                                 \
            CP16(_sA + _so, _Ab + (size_t)_r * lda + _c * 8);                 \
            CP16(_sB + _so, _Bb + (size_t)_r * ldb + _c * 8);                 \
        }                                                                     \
        asm volatile("cp.async.commit_group;" ::: "memory");                  \
    } while (0)

#define MAINLOOP()                                                            \
    PRODUCE(0); PRODUCE(1); PRODUCE(2);                                       \
    for (int i = 0; i < NT; i++) {                                            \
        asm volatile("cp.async.wait_group 2;" ::: "memory");                  \
        __syncthreads();                                                      \
        if (i + 3 < NT) PRODUCE(i + 3);                                       \
        else asm volatile("cp.async.commit_group;" ::: "memory");             \
        const uint32_t stA = sbase + (i & 3) * STAGE_B;                       \
        const uint32_t stB = stA + BOFF;                                      \
        _Pragma("unroll")                                                     \
        for (int ks = 0; ks < 2; ks++) {                                      \
            const uint32_t kbyte = (uint32_t)(ks * 32);                       \
            uint32_t a[4][4], b[8][2];                                        \
            _Pragma("unroll")                                                 \
            for (int mi = 0; mi < 4; mi++)                                    \
                ldsm4(a[mi], stA + a_off + (uint32_t)(mi * 16 * 80) + kbyte); \
            _Pragma("unroll")                                                 \
            for (int np = 0; np < 4; np++) {                                  \
                uint32_t rb[4];                                               \
                ldsm4(rb, stB + b_off + (uint32_t)(np * 16 * 80) + kbyte);    \
                b[np*2][0] = rb[0]; b[np*2][1] = rb[1];                       \
                b[np*2+1][0] = rb[2]; b[np*2+1][1] = rb[3];                   \
            }                                                                 \
            _Pragma("unroll")                                                 \
            for (int mi = 0; mi < 4; mi++)                                    \
                _Pragma("unroll")                                             \
                for (int ni = 0; ni < 8; ni++)                                \
                    mma_f16(acc[mi][ni], a[mi], b[ni]);                       \
        }                                                                     \
    }

#define DECL_COMMON()                                                         \
    extern __shared__ __half smem[];                                          \
    const uint32_t sbase = smem_u32(smem);                                    \
    const int tid = threadIdx.x, wid = tid >> 5, lane = tid & 31;             \
    const int l4 = lane >> 2, lq = lane & 3;                                  \
    const int wm = (wid >> 1) * 64, wn = (wid & 1) * 64;                      \
    const int lt = lane >> 3, lr = lane & 7;                                  \
    const uint32_t a_off = (uint32_t)((wm + (lt & 1) * 8 + lr) * 80 + (lt >> 1) * 16); \
    const uint32_t b_off = (uint32_t)((wn + (lt >> 1) * 8 + lr) * 80 + (lt & 1) * 16); \
    float acc[4][8][4];                                                       \
    _Pragma("unroll")                                                         \
    for (int i = 0; i < 4; i++)                                               \
        _Pragma("unroll")                                                     \
        for (int j = 0; j < 8; j++)                                           \
            _Pragma("unroll")                                                 \
            for (int e = 0; e < 4; e++) acc[i][j][e] = 0.f;

// coalesced half-tile store: sT[128][136] smem -> dst rows (4 thr/row, 64B each)
#define STORE_TILE_H(sT, dstbase, ldst) do {                                  \
        const int _rg = tid >> 2, _q = tid & 3;                               \
        _Pragma("unroll")                                                     \
        for (int _p = 0; _p < 4; _p++) {                                      \
            const int _r = _p * 32 + _rg;                                     \
            const __half* _s = (sT) + (size_t)_r * 136 + _q * 32;             \
            __half* _d = (dstbase) + (size_t)_r * (ldst) + _q * 32;           \
            _Pragma("unroll")                                                 \
            for (int _j = 0; _j < 4; _j++)                                    \
                *(float4*)(_d + _j * 8) = *(const float4*)(_s + _j * 8);      \
        }                                                                     \
    } while (0)

// ---------------------------------------------------------------------------
// Fused QKV projection: grid (24, 64). bx/8 selects {Q, K, V}.
// All outputs repacked through smem for fully-coalesced 64B stores.
// ---------------------------------------------------------------------------
__global__ void __launch_bounds__(128, 2)
gemm_qkv(const __half* __restrict__ X,
         const __half* __restrict__ Wq, const __half* __restrict__ Wk,
         const __half* __restrict__ Wv,
         __half* __restrict__ Q, __half* __restrict__ Kh, __half* __restrict__ Vt)
{
    const int bxs = blockIdx.x;
    const int sel = bxs >> 3;
    const int bx  = bxs & 7;
    const int by  = blockIdx.y;
    const int lda = DIM, ldb = DIM;
    const int NT  = DIM >> 5;

    DECL_COMMON();
    const __half* Ag = X + (size_t)by * 128 * lda;
    const __half* W  = (sel == 0) ? Wq : (sel == 1) ? Wk : Wv;
    const __half* Bg = W + (size_t)bx * 128 * ldb;

    MAINLOOP();

    __syncthreads();                             // pipeline smem reusable
    __half* sT = smem;                           // [128][136] halves

    if (sel < 2) {
        // repack [row][col] then coalesced store
#pragma unroll
        for (int mi = 0; mi < 4; mi++) {
            const int r0 = wm + mi * 16 + l4;
            const int r1 = r0 + 8;
#pragma unroll
            for (int ni = 0; ni < 8; ni++) {
                const int c = wn + ni * 8 + 2 * lq;
                *(__half2*)(sT + (size_t)r0 * 136 + c) = __floats2half2_rn(acc[mi][ni][0], acc[mi][ni][1]);
                *(__half2*)(sT + (size_t)r1 * 136 + c) = __floats2half2_rn(acc[mi][ni][2], acc[mi][ni][3]);
            }
        }
        __syncthreads();
        __half* C = ((sel == 0) ? Q : Kh) + (size_t)(by * 128) * DIM + bx * 128;
        STORE_TILE_H(sT, C, DIM);
    } else {
        // V: transpose [col][row] then coalesced store to Vt
#pragma unroll
        for (int mi = 0; mi < 4; mi++) {
            const int r0 = wm + mi * 16 + l4;
            const int r1 = r0 + 8;
#pragma unroll
            for (int ni = 0; ni < 8; ni++) {
                const int c = wn + ni * 8 + 2 * lq;
                sT[(size_t)c * 136 + r0]       = __float2half_rn(acc[mi][ni][0]);
                sT[(size_t)(c + 1) * 136 + r0] = __float2half_rn(acc[mi][ni][1]);
                sT[(size_t)c * 136 + r1]       = __float2half_rn(acc[mi][ni][2]);
                sT[(size_t)(c + 1) * 136 + r1] = __float2half_rn(acc[mi][ni][3]);
            }
        }
        __syncthreads();
        __half* C = Vt + (size_t)(bx * 128) * SEQ + (size_t)by * 128;
        STORE_TILE_H(sT, C, SEQ);
    }
}

// ---------------------------------------------------------------------------
// QK^T with fused block-softmax epilogue. TRIANGULAR grid: 2080 CTAs.
// P tile repacked through smem -> fully-coalesced 64B stores.
// ---------------------------------------------------------------------------
__global__ void __launch_bounds__(128, 2)
gemm_qk(const __half* __restrict__ A, const __half* __restrict__ B,
        __half* __restrict__ P, float* __restrict__ Mb, float* __restrict__ Lb)
{
    const int bid = blockIdx.x;                  // 0..2079
    int by = (int)((sqrtf(8.f * bid + 1.f) - 1.f) * 0.5f);
    while ((by + 1) * (by + 2) / 2 <= bid) by++;
    while (by * (by + 1) / 2 > bid) by--;
    const int bx = bid - by * (by + 1) / 2;

    const int lda = DIM, ldb = DIM;
    const int NT = DIM >> 5;

    DECL_COMMON();
    const __half* Ag = A + (size_t)by * 128 * lda;
    const __half* Bg = B + (size_t)bx * 128 * ldb;

    MAINLOOP();

    __syncthreads();
    float* smax = (float*)smem;                  // [2][128] floats (1KB)
    float* ssum = smax + 256;                    // [2][128] floats (1KB)
    __half* sP  = smem + 2048;                   // [128][136] halves @ +4KB

    float m0[4], m1[4];
#pragma unroll
    for (int mi = 0; mi < 4; mi++) {
        const int r0 = wm + mi * 16 + l4;
        const int r1 = r0 + 8;
        float a0 = -3.4e38f, a1 = -3.4e38f;
#pragma unroll
        for (int ni = 0; ni < 8; ni++) {
            const int c = wn + ni * 8 + 2 * lq;
            float v0 = acc[mi][ni][0] * 0.03125f;
            float v1 = acc[mi][ni][1] * 0.03125f;
            float v2 = acc[mi][ni][2] * 0.03125f;
            float v3 = acc[mi][ni][3] * 0.03125f;
            if (bx == by) {
                if (c     > r0) v0 = -1e30f;
                if (c + 1 > r0) v1 = -1e30f;
                if (c     > r1) v2 = -1e30f;
                if (c + 1 > r1) v3 = -1e30f;
            }
            acc[mi][ni][0] = v0; acc[mi][ni][1] = v1;
            acc[mi][ni][2] = v2; acc[mi][ni][3] = v3;
            a0 = fmaxf(a0, fmaxf(v0, v1));
            a1 = fmaxf(a1, fmaxf(v2, v3));
        }
        m0[mi] = a0; m1[mi] = a1;
    }
#pragma unroll
    for (int mi = 0; mi < 4; mi++) {
        m0[mi] = fmaxf(m0[mi], __shfl_xor_sync(0xffffffffu, m0[mi], 1));
        m0[mi] = fmaxf(m0[mi], __shfl_xor_sync(0xffffffffu, m0[mi], 2));
        m1[mi] = fmaxf(m1[mi], __shfl_xor_sync(0xffffffffu, m1[mi], 1));
        m1[mi] = fmaxf(m1[mi], __shfl_xor_sync(0xffffffffu, m1[mi], 2));
    }
    if (lq == 0) {
#pragma unroll
        for (int mi = 0; mi < 4; mi++) {
            const int r = wm + mi * 16 + l4;
            smax[(wid & 1) * 128 + r]     = m0[mi];
            smax[(wid & 1) * 128 + r + 8] = m1[mi];
        }
    }
    __syncthreads();
    float cm0[4], cm1[4];
#pragma unroll
    for (int mi = 0; mi < 4; mi++) {
        const int r = wm + mi * 16 + l4;
        cm0[mi] = fmaxf(smax[r],     smax[128 + r]);
        cm1[mi] = fmaxf(smax[r + 8], smax[128 + r + 8]);
    }

    // exp -> sP (conflict-free: word idx = 68*r + c/2 -> 4*l4+lq mod 32), sums
    float s0[4], s1[4];
#pragma unroll
    for (int mi = 0; mi < 4; mi++) {
        const int r0 = wm + mi * 16 + l4;
        const int r1 = r0 + 8;
        float t0 = 0.f, t1 = 0.f;
#pragma unroll
        for (int ni = 0; ni < 8; ni++) {
            const int c = wn + ni * 8 + 2 * lq;
            float e0 = __expf(acc[mi][ni][0] - cm0[mi]);
            float e1 = __expf(acc[mi][ni][1] - cm0[mi]);
            float e2 = __expf(acc[mi][ni][2] - cm1[mi]);
            float e3 = __expf(acc[mi][ni][3] - cm1[mi]);
            t0 += e0 + e1; t1 += e2 + e3;
            *(__half2*)(sP + (size_t)r0 * 136 + c) = __floats2half2_rn(e0, e1);
            *(__half2*)(sP + (size_t)r1 * 136 + c) = __floats2half2_rn(e2, e3);
        }
        s0[mi] = t0; s1[mi] = t1;
    }
#pragma unroll
    for (int mi = 0; mi < 4; mi++) {
        s0[mi] += __shfl_xor_sync(0xffffffffu, s0[mi], 1);
        s0[mi] += __shfl_xor_sync(0xffffffffu, s0[mi], 2);
        s1[mi] += __shfl_xor_sync(0xffffffffu, s1[mi], 1);
        s1[mi] += __shfl_xor_sync(0xffffffffu, s1[mi], 2);
    }
    if (lq == 0) {
#pragma unroll
        for (int mi = 0; mi < 4; mi++) {
            const int r = wm + mi * 16 + l4;
            ssum[(wid & 1) * 128 + r]     = s0[mi];
            ssum[(wid & 1) * 128 + r + 8] = s1[mi];
        }
    }
    __syncthreads();                             // covers sP writes too
    if ((wid & 1) == 0 && lq == 0) {
#pragma unroll
        for (int mi = 0; mi < 4; mi++) {
            const int r = wm + mi * 16 + l4;
            const size_t g0 = (size_t)(by * 128 + r) * 64 + bx;
            const size_t g1 = (size_t)(by * 128 + r + 8) * 64 + bx;
            Mb[g0] = cm0[mi]; Lb[g0] = ssum[r] + ssum[128 + r];
            Mb[g1] = cm1[mi]; Lb[g1] = ssum[r + 8] + ssum[128 + r + 8];
        }
    }
    // coalesced P store
    __half* Pd = P + (size_t)(by * 128) * SEQ + bx * 128;
    STORE_TILE_H(sP, Pd, SEQ);
}

// ---------------------------------------------------------------------------
__global__ void __launch_bounds__(256)
stats_k(const float* __restrict__ Mb, const float* __restrict__ Lb,
        __half* __restrict__ SC)
{
    const int row  = blockIdx.x * 8 + (threadIdx.x >> 5);
    const int lane = threadIdx.x & 31;
    const int nb   = (row >> 7) + 1;
    const size_t base = (size_t)row * 64;

    float mA = (lane      < nb) ? Mb[base + lane]      : -3.4e38f;
    float mB = (lane + 32 < nb) ? Mb[base + lane + 32] : -3.4e38f;
    float mm = fmaxf(mA, mB);
#pragma unroll
    for (int s = 16; s > 0; s >>= 1)
        mm = fmaxf(mm, __shfl_xor_sync(0xffffffffu, mm, s));

    float eA = (lane      < nb) ? __expf(mA - mm) : 0.f;
    float eB = (lane + 32 < nb) ? __expf(mB - mm) : 0.f;
    float part = (lane < nb ? Lb[base + lane] * eA : 0.f)
               + (lane + 32 < nb ? Lb[base + lane + 32] * eB : 0.f);
#pragma unroll
    for (int s = 16; s > 0; s >>= 1)
        part += __shfl_xor_sync(0xffffffffu, part, s);
    const float inv = 1.f / part;

    if (lane < nb)      SC[base + lane]      = __float2half(eA * inv);
    if (lane + 32 < nb) SC[base + lane + 32] = __float2half(eB * inv);
}

// ---------------------------------------------------------------------------
// PV with split-K LPT schedule (R13): grid (8, 80).
// ---------------------------------------------------------------------------
__global__ void __launch_bounds__(128, 2)
gemm_pv(const __half* __restrict__ Phat, const __half* __restrict__ Vt,
        const __half* __restrict__ SC, float* __restrict__ Out,
        float* __restrict__ Part)
{
    const int bx = blockIdx.x;
    const int r  = blockIdx.y;
    int by, b0, nu, dst;
    if (r < 16)      { by = 47 - r;        b0 = 0;  nu = by + 1;      dst = 0; }
    else if (r < 32) { by = 63 - (r - 16); b0 = 0;  nu = 32;          dst = 1; }
    else if (r < 64) { int p = (r - 32) >> 1;
                       if (((r - 32) & 1) == 0) { by = 31 - p; b0 = 0;  nu = by + 1;      dst = 0; }
                       else                     { by = 63 - p; b0 = 32; nu = by + 1 - 32; dst = 0; } }
    else             { by = 15 - (r - 64); b0 = 0;  nu = by + 1;      dst = 0; }

    const int lda = SEQ, ldb = SEQ;
    const int NT = nu * 4;

    DECL_COMMON();
    const __half* Ag = Phat + (size_t)by * 128 * lda + (size_t)b0 * 128;
    const __half* Bg = Vt + (size_t)bx * 128 * ldb + (size_t)b0 * 128;
    const size_t scbase = (size_t)(by * 128) * 64;

    __half2 scb[2][4][2];
#define LOADSC(b, buf) do {                                                   \
        _Pragma("unroll")                                                     \
        for (int _mi = 0; _mi < 4; _mi++) {                                   \
            const __half* _p = SC + scbase + (size_t)(wm + _mi * 16 + l4) * 64 + (b); \
            scb[buf][_mi][0] = __half2half2(_p[0]);                           \
            scb[buf][_mi][1] = __half2half2(_p[8 * 64]);                      \
        }                                                                     \
    } while (0)

    LOADSC(b0, 0);

    PRODUCE(0); PRODUCE(1); PRODUCE(2);
    for (int i = 0; i < NT; i++) {
        asm volatile("cp.async.wait_group 2;" ::: "memory");
        __syncthreads();
        if (i + 3 < NT) PRODUCE(i + 3);
        else asm volatile("cp.async.commit_group;" ::: "memory");

        if ((i & 3) == 1 && (i >> 2) + 1 < nu) LOADSC(b0 + (i >> 2) + 1, ((i >> 2) + 1) & 1);
        const int sbuf = (i >> 2) & 1;

        const uint32_t stA = sbase + (i & 3) * STAGE_B;
        const uint32_t stB = stA + BOFF;
#pragma unroll
        for (int ks = 0; ks < 2; ks++) {
            const uint32_t kbyte = (uint32_t)(ks * 32);
            uint32_t a[4][4], b[8][2];
#pragma unroll
            for (int mi = 0; mi < 4; mi++) {
                ldsm4(a[mi], stA + a_off + (uint32_t)(mi * 16 * 80) + kbyte);
                a[mi][0] = hmul2_u(a[mi][0], scb[sbuf][mi][0]);
                a[mi][2] = hmul2_u(a[mi][2], scb[sbuf][mi][0]);
                a[mi][1] = hmul2_u(a[mi][1], scb[sbuf][mi][1]);
                a[mi][3] = hmul2_u(a[mi][3], scb[sbuf][mi][1]);
            }
#pragma unroll
            for (int np = 0; np < 4; np++) {
                uint32_t rb[4];
                ldsm4(rb, stB + b_off + (uint32_t)(np * 16 * 80) + kbyte);
                b[np*2][0] = rb[0]; b[np*2][1] = rb[1];
                b[np*2+1][0] = rb[2]; b[np*2+1][1] = rb[3];
            }
#pragma unroll
            for (int mi = 0; mi < 4; mi++)
#pragma unroll
                for (int ni = 0; ni < 8; ni++)
                    mma_f16(acc[mi][ni], a[mi], b[ni]);
        }
    }
#undef LOADSC

    float* C = dst ? (Part - (size_t)6144 * DIM) : Out;
#pragma unroll
    for (int mi = 0; mi < 4; mi++) {
        const int gr0 = by * 128 + wm + mi * 16 + l4;
        const int gr1 = gr0 + 8;
#pragma unroll
        for (int ni = 0; ni < 8; ni++) {
            const int gc = bx * 128 + wn + ni * 8 + 2 * lq;
            *(float2*)(C + (size_t)gr0 * DIM + gc) = make_float2(acc[mi][ni][0], acc[mi][ni][1]);
            *(float2*)(C + (size_t)gr1 * DIM + gc) = make_float2(acc[mi][ni][2], acc[mi][ni][3]);
        }
    }
}

// add split-K partials into out rows [6144, 8192)
__global__ void __launch_bounds__(256)
pv_fixup(float* __restrict__ Out, const float* __restrict__ Part)
{
    const size_t i = ((size_t)blockIdx.x * 256 + threadIdx.x) * 4;
    float4 a = *(const float4*)(Out + (size_t)6144 * DIM + i);
    float4 b = *(const float4*)(Part + i);
    a.x += b.x; a.y += b.y; a.z += b.z; a.w += b.w;
    *(float4*)(Out + (size_t)6144 * DIM + i) = a;
}

// ---------------------------------------------------------------------------
__global__ void __launch_bounds__(256)
conv_all(const float* __restrict__ x,  const float* __restrict__ wq,
         const float* __restrict__ wk, const float* __restrict__ wv,
         __half* __restrict__ hX,  __half* __restrict__ hWq,
         __half* __restrict__ hWk, __half* __restrict__ hWv)
{
    const long long NX = (long long)SEQ * DIM / 4;
    const long long NW = (long long)DIM * DIM / 4;
    long long f4 = (long long)blockIdx.x * 256 + threadIdx.x;
    const float* s; __half* d; long long off;
    if      (f4 < NX)          { s = x;  d = hX;  off = f4; }
    else if (f4 < NX + NW)     { s = wq; d = hWq; off = f4 - NX; }
    else if (f4 < NX + 2 * NW) { s = wk; d = hWk; off = f4 - NX - NW; }
    else                       { s = wv; d = hWv; off = f4 - NX - 2 * NW; }
    float4 v = *(const float4*)(s + off * 4);
    *(__half2*)(d + off * 4)     = __floats2half2_rn(v.x, v.y);
    *(__half2*)(d + off * 4 + 2) = __floats2half2_rn(v.z, v.w);
}

// ---------------------------------------------------------------------------
extern "C" void kernel_launch(void* const* d_in, const int* in_sizes, int n_in,
                              void* d_out, int out_size)
{
    const float* x  = (const float*)d_in[0];
    const float* wq = (const float*)d_in[1];
    const float* wk = (const float*)d_in[2];
    const float* wv = (const float*)d_in[3];
    float* out = (float*)d_out;

    __half *hX, *hWq, *hWk, *hWv, *hQ, *hK, *hVt, *hP, *sc;
    float *Mb, *Lb, *part;
    cudaGetSymbolAddress((void**)&hX,   g_hX);
    cudaGetSymbolAddress((void**)&hWq,  g_hWq);
    cudaGetSymbolAddress((void**)&hWk,  g_hWk);
    cudaGetSymbolAddress((void**)&hWv,  g_hWv);
    cudaGetSymbolAddress((void**)&hQ,   g_hQ);
    cudaGetSymbolAddress((void**)&hK,   g_hK);
    cudaGetSymbolAddress((void**)&hVt,  g_hVt);
    cudaGetSymbolAddress((void**)&hP,   g_hP);
    cudaGetSymbolAddress((void**)&sc,   g_sc);
    cudaGetSymbolAddress((void**)&Mb,   g_Mb);
    cudaGetSymbolAddress((void**)&Lb,   g_Lb);
    cudaGetSymbolAddress((void**)&part, g_part);

    const int SMEM_DYN = 4 * STAGE_B;            // 81920 bytes
    cudaFuncSetAttribute(gemm_qkv, cudaFuncAttributeMaxDynamicSharedMemorySize, SMEM_DYN);
    cudaFuncSetAttribute(gemm_qk,  cudaFuncAttributeMaxDynamicSharedMemorySize, SMEM_DYN);
    cudaFuncSetAttribute(gemm_pv,  cudaFuncAttributeMaxDynamicSharedMemorySize, SMEM_DYN);

    const long long NCONV = (long long)SEQ * DIM / 4 + 3LL * DIM * DIM / 4;
    conv_all<<<(unsigned)((NCONV + 255) / 256), 256>>>(x, wq, wk, wv, hX, hWq, hWk, hWv);

    dim3 gthr(128);

    gemm_qkv<<<dim3(24, 64), gthr, SMEM_DYN>>>(hX, hWq, hWk, hWv, hQ, hK, hVt);

    gemm_qk<<<2080, gthr, SMEM_DYN>>>(hQ, hK, hP, Mb, Lb);

    stats_k<<<SEQ / 8, 256>>>(Mb, Lb, sc);

    gemm_pv<<<dim3(8, 80), gthr, SMEM_DYN>>>(hP, hVt, sc, out, part);

    pv_fixup<<<2048 * DIM / 1024, 256>>>(out, part);
}